// round 12
// baseline (speedup 1.0000x reference)
#include <cuda_runtime.h>
#include <cuda_fp16.h>
#include <cstdint>
#include <cstddef>

#define NN 8192
#define OUT_DIM 64
#define IN_DIM 256
#define KB 4                  // K-split across grid.x
#define KSLAB (NN / KB)       // 2048
#define MTILE 64              // rows per CTA (4 warps x 16)
#define NWARP 4
#define APITCH 68             // smem ints per staged A row
#define NIT (KSLAB / 64)      // 32 stages
#define ASTB (16 * APITCH * 4)   // bytes per A stage per warp = 4352

// ---------------- device scratch ----------------
__device__ float g_f1[NN];
__device__ float g_f2[NN];
__device__ float2 g_EG1[NN];                 // {S*exp(f1), S*exp(0.2 f1)}
__device__ float2 g_EG2[NN];                 // {exp(f2), exp(0.2 f2)}
__device__ uint4 g_Bfrag[512 * 4 * 32];      // Wh in fp16 mma-B-fragment layout (1 MB)
__device__ float g_num[(size_t)KB * NN * OUT_DIM];
__device__ float g_den[KB * NN];

// ---------------- helpers ----------------
__device__ __forceinline__ void mma16816(float* d, uint32_t a0, uint32_t a1,
                                         uint32_t a2, uint32_t a3,
                                         uint32_t b0, uint32_t b1) {
    asm volatile(
        "mma.sync.aligned.m16n8k16.row.col.f32.f16.f16.f32 "
        "{%0,%1,%2,%3},{%4,%5,%6,%7},{%8,%9},{%0,%1,%2,%3};"
        : "+f"(d[0]), "+f"(d[1]), "+f"(d[2]), "+f"(d[3])
        : "r"(a0), "r"(a1), "r"(a2), "r"(a3), "r"(b0), "r"(b1));
}
__device__ __forceinline__ uint32_t packh2(float lo, float hi) {
    __half2 h = __floats2half2_rn(lo, hi);
    return *reinterpret_cast<uint32_t*>(&h);
}
__device__ __forceinline__ uint32_t s2u(const void* p) {
    uint32_t a;
    asm("{ .reg .u64 t; cvta.to.shared.u64 t, %1; cvt.u32.u64 %0, t; }" : "=r"(a) : "l"(p));
    return a;
}
__device__ __forceinline__ void cpasync16(uint32_t smem, const void* g) {
    asm volatile("cp.async.cg.shared.global [%0], [%1], 16;" :: "r"(smem), "l"(g) : "memory");
}
#define CP_COMMIT() asm volatile("cp.async.commit_group;" ::: "memory")
#define CP_WAIT1()  asm volatile("cp.async.wait_group 1;" ::: "memory")

// ================= K1: Wh = h@W, f1/f2, and frag-pack (fused) =================
extern __shared__ float k1sm[];
__global__ void __launch_bounds__(256) k1_wh(const float* __restrict__ h,
                                             const float* __restrict__ W,
                                             const float* __restrict__ a) {
    float* Ws = k1sm;                      // [256][64], reused as Wh tile after compute
    float* hs = k1sm + IN_DIM * OUT_DIM;   // [64][260]
    int tid = threadIdx.x;
    int rg = tid >> 4;                     // 16 row groups x 4 rows
    int cg = tid & 15;                     // 16 col groups x 4 cols
    int row0 = blockIdx.x * 64;

    for (int t = tid; t < IN_DIM * OUT_DIM / 4; t += 256)
        ((float4*)Ws)[t] = ((const float4*)W)[t];
    for (int t = tid; t < 64 * IN_DIM / 4; t += 256) {
        int r = t >> 6, c = (t & 63) * 4;
        *(float4*)(hs + r * 260 + c) = *(const float4*)(h + (((size_t)(row0 + r)) << 8) + c);
    }
    __syncthreads();

    float4 acc[4];
#pragma unroll
    for (int r = 0; r < 4; r++) acc[r] = make_float4(0.f, 0.f, 0.f, 0.f);

#pragma unroll 2
    for (int kk = 0; kk < IN_DIM; kk += 4) {
        float4 w0 = *(const float4*)(Ws + (kk + 0) * OUT_DIM + cg * 4);
        float4 w1 = *(const float4*)(Ws + (kk + 1) * OUT_DIM + cg * 4);
        float4 w2 = *(const float4*)(Ws + (kk + 2) * OUT_DIM + cg * 4);
        float4 w3 = *(const float4*)(Ws + (kk + 3) * OUT_DIM + cg * 4);
#pragma unroll
        for (int r = 0; r < 4; r++) {
            float4 hq = *(const float4*)(hs + (rg * 4 + r) * 260 + kk);
            acc[r].x = fmaf(hq.x, w0.x, acc[r].x);
            acc[r].y = fmaf(hq.x, w0.y, acc[r].y);
            acc[r].z = fmaf(hq.x, w0.z, acc[r].z);
            acc[r].w = fmaf(hq.x, w0.w, acc[r].w);
            acc[r].x = fmaf(hq.y, w1.x, acc[r].x);
            acc[r].y = fmaf(hq.y, w1.y, acc[r].y);
            acc[r].z = fmaf(hq.y, w1.z, acc[r].z);
            acc[r].w = fmaf(hq.y, w1.w, acc[r].w);
            acc[r].x = fmaf(hq.z, w2.x, acc[r].x);
            acc[r].y = fmaf(hq.z, w2.y, acc[r].y);
            acc[r].z = fmaf(hq.z, w2.z, acc[r].z);
            acc[r].w = fmaf(hq.z, w2.w, acc[r].w);
            acc[r].x = fmaf(hq.w, w3.x, acc[r].x);
            acc[r].y = fmaf(hq.w, w3.y, acc[r].y);
            acc[r].z = fmaf(hq.w, w3.z, acc[r].z);
            acc[r].w = fmaf(hq.w, w3.w, acc[r].w);
        }
    }

    // f1/f2 reduction across 16 col-groups
    float4 a1v = *(const float4*)(a + cg * 4);
    float4 a2v = *(const float4*)(a + OUT_DIM + cg * 4);
#pragma unroll
    for (int r = 0; r < 4; r++) {
        int row = row0 + rg * 4 + r;
        float s1 = acc[r].x * a1v.x + acc[r].y * a1v.y + acc[r].z * a1v.z + acc[r].w * a1v.w;
        float s2 = acc[r].x * a2v.x + acc[r].y * a2v.y + acc[r].z * a2v.z + acc[r].w * a2v.w;
#pragma unroll
        for (int o = 1; o < 16; o <<= 1) {
            s1 += __shfl_xor_sync(~0u, s1, o);
            s2 += __shfl_xor_sync(~0u, s2, o);
        }
        if (cg == 0) { g_f1[row] = s1; g_f2[row] = s2; }
    }

    // ---- fused frag-pack: acc -> smem Wh tile -> g_Bfrag ----
    __syncthreads();   // everyone done reading Ws
    float* Whs = Ws;   // [64][68] pitch
#pragma unroll
    for (int r = 0; r < 4; r++)
        *(float4*)(Whs + (rg * 4 + r) * 68 + cg * 4) = acc[r];
    __syncthreads();

#pragma unroll
    for (int q = 0; q < 2; q++) {
        int idx = q * 256 + tid;        // 512 frag slots: 4 kc x 4 p x 32 lanes
        int kcl = idx >> 7;
        int rem = idx & 127;
        int p = rem >> 5, lane = rem & 31;
        int lk = kcl * 16 + (lane & 3) * 2;
        int n0 = p * 16 + (lane >> 2);
        int n1 = n0 + 8;
        uint4 o;
        o.x = packh2(Whs[lk * 68 + n0],       Whs[(lk + 1) * 68 + n0]);
        o.y = packh2(Whs[(lk + 8) * 68 + n0], Whs[(lk + 9) * 68 + n0]);
        o.z = packh2(Whs[lk * 68 + n1],       Whs[(lk + 1) * 68 + n1]);
        o.w = packh2(Whs[(lk + 8) * 68 + n1], Whs[(lk + 9) * 68 + n1]);
        g_Bfrag[((blockIdx.x * 4 + kcl) * 4 + p) * 32 + lane] = o;
    }
}

// ========== K1c: exp vectors (32 blocks; each redundantly computes global max) ==========
__global__ void __launch_bounds__(256) k1c(void) {
    __shared__ float m1s[8], m2s[8], lss;
    int tid = threadIdx.x;
    float m1 = -1e30f, m2 = -1e30f;
    for (int i = tid; i < NN; i += 256) {
        m1 = fmaxf(m1, g_f1[i]);
        m2 = fmaxf(m2, g_f2[i]);
    }
#pragma unroll
    for (int o = 16; o; o >>= 1) {
        m1 = fmaxf(m1, __shfl_xor_sync(~0u, m1, o));
        m2 = fmaxf(m2, __shfl_xor_sync(~0u, m2, o));
    }
    if ((tid & 31) == 0) { m1s[tid >> 5] = m1; m2s[tid >> 5] = m2; }
    __syncthreads();
    if (tid == 0) {
        float a1 = m1s[0], a2 = m2s[0];
#pragma unroll
        for (int i = 1; i < 8; i++) { a1 = fmaxf(a1, m1s[i]); a2 = fmaxf(a2, m2s[i]); }
        lss = logf(49000.f) - a1 - a2;
    }
    __syncthreads();
    float ls = lss;
    int i = blockIdx.x * 256 + tid;
    float f1 = g_f1[i], f2 = g_f2[i];
    g_EG1[i] = make_float2(expf(f1 + ls), expf(0.2f * f1 + ls));
    g_EG2[i] = make_float2(expf(f2), expf(0.2f * f2));
}

// ========== dummy kernel: keeps k2_attn as the 4th launch for ncu ==========
__global__ void dnoop(void) {}

// ================= K2: masked attention, HMMA, 128-thr CTA x 4/SM =================
// smem bytes: EG2 [0,16384) | per-warp A rings [16384, 51200)
#define SM_A0 16384
extern __shared__ char k2smraw[];
__global__ void __launch_bounds__(128, 4) k2_attn(const int* __restrict__ A) {
    float2* EG2s = (float2*)k2smraw;
    int tid = threadIdx.x, wid = tid >> 5, lane = tid & 31;
    int kb = blockIdx.x;
    int rowBase = blockIdx.y * MTILE;
    uint32_t sb = s2u(k2smraw);

    for (int i = tid; i < KSLAB; i += 128) EG2s[i] = g_EG2[kb * KSLAB + i];

    int r_lo = lane >> 2;
    int q2 = (lane & 3) * 2;
    int myrow = rowBase + wid * 16;
    float2 eg1a = g_EG1[myrow + r_lo];
    float2 eg1b = g_EG1[myrow + r_lo + 8];

    float acc[8][4];
#pragma unroll
    for (int n = 0; n < 8; n++)
#pragma unroll
        for (int c = 0; c < 4; c++) acc[n][c] = 0.f;
    float dn0 = 0.f, dn1 = 0.f;

    const int* Arow = A + (size_t)myrow * NN + kb * KSLAB;
    int ldRow = lane >> 4;                 // 0..1
    int ldSeg = (lane & 15) * 4;           // int offset 0..60
    uint32_t aRing = sb + SM_A0 + wid * (2 * ASTB);
    const uint4* Bbase = g_Bfrag + (size_t)kb * (KSLAB / 16) * 128 + lane;

#define A_STAGE(s) do {                                                           \
        int _c0 = (s) * 64;                                                       \
        uint32_t _ad = aRing + ((s) & 1) * ASTB;                                  \
        _Pragma("unroll")                                                         \
        for (int _L = 0; _L < 8; _L++)                                            \
            cpasync16(_ad + ((_L * 2 + ldRow) * APITCH + ldSeg) * 4,              \
                      Arow + (size_t)(_L * 2 + ldRow) * NN + _c0 + ldSeg);        \
        CP_COMMIT();                                                              \
    } while (0)

    A_STAGE(0);
    A_STAGE(1);

    __syncthreads();   // EG2s visibility (once)

    // B prefetch for chunk 0
    uint4 Bpf[4];
#pragma unroll
    for (int p = 0; p < 4; p++) Bpf[p] = __ldg(Bbase + p * 32);

#pragma unroll 1
    for (int it = 0; it < NIT; ++it) {
        CP_WAIT1();
        __syncwarp();

        const int* Aw = (const int*)(k2smraw + SM_A0 + wid * (2 * ASTB) + (it & 1) * ASTB);

#pragma unroll
        for (int ck = 0; ck < 4; ++ck) {
            int c = it * 4 + ck;
            // consume current prefetch, immediately start next
            uint4 B0 = Bpf[0], B1 = Bpf[1], B2 = Bpf[2], B3 = Bpf[3];
            if (c + 1 < 4 * NIT) {
                const uint4* Bp = Bbase + (size_t)(c + 1) * 128;
#pragma unroll
                for (int p = 0; p < 4; p++) Bpf[p] = __ldg(Bp + p * 32);
            }

            int cl = c * 16;
            float4 egA = *(const float4*)(&EG2s[cl + q2]);
            float4 egB = *(const float4*)(&EG2s[cl + q2 + 8]);
            int base = ck * 16 + q2;
            int2 aL0 = *(const int2*)(Aw + r_lo * APITCH + base);
            int2 aL1 = *(const int2*)(Aw + r_lo * APITCH + base + 8);
            int2 aH0 = *(const int2*)(Aw + (r_lo + 8) * APITCH + base);
            int2 aH1 = *(const int2*)(Aw + (r_lo + 8) * APITCH + base + 8);

            float w00 = (aL0.x > 0) ? fmaxf(eg1a.x * egA.x, eg1a.y * egA.y) : 0.f;
            float w01 = (aL0.y > 0) ? fmaxf(eg1a.x * egA.z, eg1a.y * egA.w) : 0.f;
            float w02 = (aL1.x > 0) ? fmaxf(eg1a.x * egB.x, eg1a.y * egB.y) : 0.f;
            float w03 = (aL1.y > 0) ? fmaxf(eg1a.x * egB.z, eg1a.y * egB.w) : 0.f;
            float w10 = (aH0.x > 0) ? fmaxf(eg1b.x * egA.x, eg1b.y * egA.y) : 0.f;
            float w11 = (aH0.y > 0) ? fmaxf(eg1b.x * egA.z, eg1b.y * egA.w) : 0.f;
            float w12 = (aH1.x > 0) ? fmaxf(eg1b.x * egB.x, eg1b.y * egB.y) : 0.f;
            float w13 = (aH1.y > 0) ? fmaxf(eg1b.x * egB.z, eg1b.y * egB.w) : 0.f;

            dn0 += (w00 + w01) + (w02 + w03);
            dn1 += (w10 + w11) + (w12 + w13);

            uint32_t a0 = packh2(w00, w01);
            uint32_t a1 = packh2(w10, w11);
            uint32_t a2 = packh2(w02, w03);
            uint32_t a3 = packh2(w12, w13);

            mma16816(acc[0], a0, a1, a2, a3, B0.x, B0.y);
            mma16816(acc[1], a0, a1, a2, a3, B0.z, B0.w);
            mma16816(acc[2], a0, a1, a2, a3, B1.x, B1.y);
            mma16816(acc[3], a0, a1, a2, a3, B1.z, B1.w);
            mma16816(acc[4], a0, a1, a2, a3, B2.x, B2.y);
            mma16816(acc[5], a0, a1, a2, a3, B2.z, B2.w);
            mma16816(acc[6], a0, a1, a2, a3, B3.x, B3.y);
            mma16816(acc[7], a0, a1, a2, a3, B3.z, B3.w);
        }
        __syncwarp();
        if (it + 2 < NIT) A_STAGE(it + 2);
        else CP_COMMIT();     // keep wait_group accounting uniform
    }

    // denominator (fp32-exact)
    dn0 += __shfl_xor_sync(~0u, dn0, 1); dn0 += __shfl_xor_sync(~0u, dn0, 2);
    dn1 += __shfl_xor_sync(~0u, dn1, 1); dn1 += __shfl_xor_sync(~0u, dn1, 2);
    if ((lane & 3) == 0) {
        g_den[kb * NN + myrow + r_lo] = dn0;
        g_den[kb * NN + myrow + r_lo + 8] = dn1;
    }
    // numerator partials
    float* np = g_num + ((size_t)kb * NN + myrow) * OUT_DIM;
#pragma unroll
    for (int nt = 0; nt < 8; nt++) {
        int col = nt * 8 + q2;
        *(float2*)(np + (size_t)r_lo * OUT_DIM + col)       = make_float2(acc[nt][0], acc[nt][1]);
        *(float2*)(np + (size_t)(r_lo + 8) * OUT_DIM + col) = make_float2(acc[nt][2], acc[nt][3]);
    }
}

// ================= K3: reduce, normalize, elu (8 floats/thread) =================
__global__ void k3_fin(float* __restrict__ out) {
    int gid = blockIdx.x * 256 + threadIdx.x;
    int base = gid * 8;
    int row = base >> 6;
    float4 s0 = make_float4(0.f, 0.f, 0.f, 0.f);
    float4 s1 = make_float4(0.f, 0.f, 0.f, 0.f);
    float d = 0.f;
#pragma unroll
    for (int c = 0; c < KB; c++) {
        const float* p = g_num + (size_t)c * NN * OUT_DIM + base;
        float4 v0 = *(const float4*)(p);
        float4 v1 = *(const float4*)(p + 4);
        s0.x += v0.x; s0.y += v0.y; s0.z += v0.z; s0.w += v0.w;
        s1.x += v1.x; s1.y += v1.y; s1.z += v1.z; s1.w += v1.w;
        d += g_den[c * NN + row];
    }
    float inv = 1.f / d;
    float4 o0, o1;
    o0.x = s0.x * inv; o0.y = s0.y * inv; o0.z = s0.z * inv; o0.w = s0.w * inv;
    o1.x = s1.x * inv; o1.y = s1.y * inv; o1.z = s1.z * inv; o1.w = s1.w * inv;
    o0.x = o0.x > 0.f ? o0.x : expm1f(o0.x);
    o0.y = o0.y > 0.f ? o0.y : expm1f(o0.y);
    o0.z = o0.z > 0.f ? o0.z : expm1f(o0.z);
    o0.w = o0.w > 0.f ? o0.w : expm1f(o0.w);
    o1.x = o1.x > 0.f ? o1.x : expm1f(o1.x);
    o1.y = o1.y > 0.f ? o1.y : expm1f(o1.y);
    o1.z = o1.z > 0.f ? o1.z : expm1f(o1.z);
    o1.w = o1.w > 0.f ? o1.w : expm1f(o1.w);
    *(float4*)(out + base) = o0;
    *(float4*)(out + base + 4) = o1;
}

// ================= launch =================
extern "C" void kernel_launch(void* const* d_in, const int* in_sizes, int n_in,
                              void* d_out, int out_size) {
    const float* h = nullptr; const int* A = nullptr;
    const float* W = nullptr; const float* a = nullptr;
    for (int i = 0; i < n_in; i++) {
        if      (in_sizes[i] == NN * IN_DIM)      h = (const float*)d_in[i];
        else if (in_sizes[i] == IN_DIM * OUT_DIM) W = (const float*)d_in[i];
        else if (in_sizes[i] == 2 * OUT_DIM)      a = (const float*)d_in[i];
        else                                      A = (const int*)d_in[i];
    }
    float* out = (float*)d_out;

    const int k1_smem = (IN_DIM * OUT_DIM + 64 * 260) * (int)sizeof(float);  // 132096
    cudaFuncSetAttribute(k1_wh, cudaFuncAttributeMaxDynamicSharedMemorySize, k1_smem);
    const int k2_smem = SM_A0 + NWARP * 2 * ASTB;   // 16384 + 34816 = 51200
    cudaFuncSetAttribute(k2_attn, cudaFuncAttributeMaxDynamicSharedMemorySize, k2_smem);

    k1_wh<<<NN / 64, 256, k1_smem>>>(h, W, a);
    k1c<<<NN / 256, 256>>>();
    dnoop<<<1, 32>>>();                       // position k2 as 4th launch for ncu
    dim3 g2(KB, NN / MTILE);
    k2_attn<<<g2, 128, k2_smem>>>(A);
    k3_fin<<<(NN * OUT_DIM) / 2048, 256>>>(out);
}

// round 13
// speedup vs baseline: 1.0493x; 1.0493x over previous
#include <cuda_runtime.h>
#include <cuda_fp16.h>
#include <cstdint>
#include <cstddef>

#define NN 8192
#define OUT_DIM 64
#define IN_DIM 256
#define KB 4                  // K-split across grid.x
#define KSLAB (NN / KB)       // 2048
#define MTILE 128             // rows per CTA (8 warps x 16)
#define APITCH 68             // smem ints per staged A row
#define NIT (KSLAB / 64)      // 32 stages
#define ASTB (16 * APITCH * 4)   // bytes per A stage per warp = 4352

// ---------------- device scratch ----------------
__device__ float g_f1[NN];
__device__ float g_f2[NN];
__device__ __half g_E2h[NN];                 // exp(f2 - m2 + lnc)
__device__ __half g_G2h[NN];                 // exp(0.2(f2 - m2) + lnc)
__device__ __half g_rh[NN];                  // exp(-0.8(f1 + m2))
__device__ uint4 g_Bfrag[512 * 4 * 32];      // Wh in fp16 mma-B-fragment layout (1 MB)
__device__ float g_num[(size_t)KB * NN * OUT_DIM];
__device__ float g_den[KB * NN];

// ---------------- helpers ----------------
__device__ __forceinline__ void mma16816(float* d, uint32_t a0, uint32_t a1,
                                         uint32_t a2, uint32_t a3,
                                         uint32_t b0, uint32_t b1) {
    asm volatile(
        "mma.sync.aligned.m16n8k16.row.col.f32.f16.f16.f32 "
        "{%0,%1,%2,%3},{%4,%5,%6,%7},{%8,%9},{%0,%1,%2,%3};"
        : "+f"(d[0]), "+f"(d[1]), "+f"(d[2]), "+f"(d[3])
        : "r"(a0), "r"(a1), "r"(a2), "r"(a3), "r"(b0), "r"(b1));
}
__device__ __forceinline__ uint32_t packh2(float lo, float hi) {
    __half2 h = __floats2half2_rn(lo, hi);
    return *reinterpret_cast<uint32_t*>(&h);
}
__device__ __forceinline__ uint32_t h2u(__half2 h) {
    return *reinterpret_cast<uint32_t*>(&h);
}
// mask for a packed half2 pair from two 0/1 ints
__device__ __forceinline__ uint32_t msk2(int2 v) {
    return (uint32_t)v.x * 0xFFFFu + (uint32_t)v.y * 0xFFFF0000u;
}
__device__ __forceinline__ uint32_t s2u(const void* p) {
    uint32_t a;
    asm("{ .reg .u64 t; cvta.to.shared.u64 t, %1; cvt.u32.u64 %0, t; }" : "=r"(a) : "l"(p));
    return a;
}
__device__ __forceinline__ void cpasync16(uint32_t smem, const void* g) {
    asm volatile("cp.async.cg.shared.global [%0], [%1], 16;" :: "r"(smem), "l"(g) : "memory");
}
#define CP_COMMIT() asm volatile("cp.async.commit_group;" ::: "memory")
#define CP_WAIT1()  asm volatile("cp.async.wait_group 1;" ::: "memory")

// ================= K1: Wh = h@W, f1/f2, and frag-pack (fused) =================
extern __shared__ float k1sm[];
__global__ void __launch_bounds__(256) k1_wh(const float* __restrict__ h,
                                             const float* __restrict__ W,
                                             const float* __restrict__ a) {
    float* Ws = k1sm;                      // [256][64], reused as Wh tile after compute
    float* hs = k1sm + IN_DIM * OUT_DIM;   // [64][260]
    int tid = threadIdx.x;
    int rg = tid >> 4;                     // 16 row groups x 4 rows
    int cg = tid & 15;                     // 16 col groups x 4 cols
    int row0 = blockIdx.x * 64;

    for (int t = tid; t < IN_DIM * OUT_DIM / 4; t += 256)
        ((float4*)Ws)[t] = ((const float4*)W)[t];
    for (int t = tid; t < 64 * IN_DIM / 4; t += 256) {
        int r = t >> 6, c = (t & 63) * 4;
        *(float4*)(hs + r * 260 + c) = *(const float4*)(h + (((size_t)(row0 + r)) << 8) + c);
    }
    __syncthreads();

    float4 acc[4];
#pragma unroll
    for (int r = 0; r < 4; r++) acc[r] = make_float4(0.f, 0.f, 0.f, 0.f);

#pragma unroll 2
    for (int kk = 0; kk < IN_DIM; kk += 4) {
        float4 w0 = *(const float4*)(Ws + (kk + 0) * OUT_DIM + cg * 4);
        float4 w1 = *(const float4*)(Ws + (kk + 1) * OUT_DIM + cg * 4);
        float4 w2 = *(const float4*)(Ws + (kk + 2) * OUT_DIM + cg * 4);
        float4 w3 = *(const float4*)(Ws + (kk + 3) * OUT_DIM + cg * 4);
#pragma unroll
        for (int r = 0; r < 4; r++) {
            float4 hq = *(const float4*)(hs + (rg * 4 + r) * 260 + kk);
            acc[r].x = fmaf(hq.x, w0.x, acc[r].x);
            acc[r].y = fmaf(hq.x, w0.y, acc[r].y);
            acc[r].z = fmaf(hq.x, w0.z, acc[r].z);
            acc[r].w = fmaf(hq.x, w0.w, acc[r].w);
            acc[r].x = fmaf(hq.y, w1.x, acc[r].x);
            acc[r].y = fmaf(hq.y, w1.y, acc[r].y);
            acc[r].z = fmaf(hq.y, w1.z, acc[r].z);
            acc[r].w = fmaf(hq.y, w1.w, acc[r].w);
            acc[r].x = fmaf(hq.z, w2.x, acc[r].x);
            acc[r].y = fmaf(hq.z, w2.y, acc[r].y);
            acc[r].z = fmaf(hq.z, w2.z, acc[r].z);
            acc[r].w = fmaf(hq.z, w2.w, acc[r].w);
            acc[r].x = fmaf(hq.w, w3.x, acc[r].x);
            acc[r].y = fmaf(hq.w, w3.y, acc[r].y);
            acc[r].z = fmaf(hq.w, w3.z, acc[r].z);
            acc[r].w = fmaf(hq.w, w3.w, acc[r].w);
        }
    }

    // f1/f2 reduction across 16 col-groups
    float4 a1v = *(const float4*)(a + cg * 4);
    float4 a2v = *(const float4*)(a + OUT_DIM + cg * 4);
#pragma unroll
    for (int r = 0; r < 4; r++) {
        int row = row0 + rg * 4 + r;
        float s1 = acc[r].x * a1v.x + acc[r].y * a1v.y + acc[r].z * a1v.z + acc[r].w * a1v.w;
        float s2 = acc[r].x * a2v.x + acc[r].y * a2v.y + acc[r].z * a2v.z + acc[r].w * a2v.w;
#pragma unroll
        for (int o = 1; o < 16; o <<= 1) {
            s1 += __shfl_xor_sync(~0u, s1, o);
            s2 += __shfl_xor_sync(~0u, s2, o);
        }
        if (cg == 0) { g_f1[row] = s1; g_f2[row] = s2; }
    }

    // ---- fused frag-pack: acc -> smem Wh tile -> g_Bfrag ----
    __syncthreads();   // everyone done reading Ws
    float* Whs = Ws;   // [64][68] pitch
#pragma unroll
    for (int r = 0; r < 4; r++)
        *(float4*)(Whs + (rg * 4 + r) * 68 + cg * 4) = acc[r];
    __syncthreads();

#pragma unroll
    for (int q = 0; q < 2; q++) {
        int idx = q * 256 + tid;        // 512 frag slots: 4 kc x 4 p x 32 lanes
        int kcl = idx >> 7;
        int rem = idx & 127;
        int p = rem >> 5, lane = rem & 31;
        int lk = kcl * 16 + (lane & 3) * 2;
        int n0 = p * 16 + (lane >> 2);
        int n1 = n0 + 8;
        uint4 o;
        o.x = packh2(Whs[lk * 68 + n0],       Whs[(lk + 1) * 68 + n0]);
        o.y = packh2(Whs[(lk + 8) * 68 + n0], Whs[(lk + 9) * 68 + n0]);
        o.z = packh2(Whs[lk * 68 + n1],       Whs[(lk + 1) * 68 + n1]);
        o.w = packh2(Whs[(lk + 8) * 68 + n1], Whs[(lk + 9) * 68 + n1]);
        g_Bfrag[((blockIdx.x * 4 + kcl) * 4 + p) * 32 + lane] = o;
    }
}

// ========== K1c: scaled exp vectors (row factor cancelled out of softmax) ==========
__global__ void __launch_bounds__(256) k1c(void) {
    __shared__ float m1s[8], m2s[8], mm1, mm2;
    int tid = threadIdx.x;
    float m1 = -1e30f, m2 = -1e30f;
    for (int i = tid; i < NN; i += 256) {
        m1 = fmaxf(m1, g_f1[i]);
        m2 = fmaxf(m2, g_f2[i]);
    }
#pragma unroll
    for (int o = 16; o; o >>= 1) {
        m1 = fmaxf(m1, __shfl_xor_sync(~0u, m1, o));
        m2 = fmaxf(m2, __shfl_xor_sync(~0u, m2, o));
    }
    if ((tid & 31) == 0) { m1s[tid >> 5] = m1; m2s[tid >> 5] = m2; }
    __syncthreads();
    if (tid == 0) {
        float a1 = m1s[0], a2 = m2s[0];
#pragma unroll
        for (int i = 1; i < 8; i++) { a1 = fmaxf(a1, m1s[i]); a2 = fmaxf(a2, m2s[i]); }
        mm1 = a1; mm2 = a2;
    }
    __syncthreads();
    float M2 = mm2;
    const float lnc = 0.5f * logf(49000.f);
    int i = blockIdx.x * 256 + tid;
    float f1 = g_f1[i], f2 = g_f2[i];
    g_E2h[i] = __float2half(expf(f2 - M2 + lnc));
    g_G2h[i] = __float2half(expf(0.2f * (f2 - M2) + lnc));
    g_rh[i]  = __float2half(expf(-0.8f * (f1 + M2)));
}

// ========== dummy kernel: keeps k2_attn as the 4th launch for ncu ==========
__global__ void dnoop(void) {}

// ================= K2: masked attention, all-fp16 weight path, den via ones-MMA =================
// smem bytes: E2h [0,4096) | G2h [4096,8192) | per-warp A rings [8192, 77824)
#define SM_G2 4096
#define SM_A0 8192
extern __shared__ char k2smraw[];
__global__ void __launch_bounds__(256, 2) k2_attn(const int* __restrict__ A) {
    int tid = threadIdx.x, wid = tid >> 5, lane = tid & 31;
    int kb = blockIdx.x;
    int rowBase = blockIdx.y * MTILE;
    uint32_t sb = s2u(k2smraw);

    // stage E2h/G2h slabs (4 KB each)
    {
        const uint4* se = (const uint4*)(g_E2h + (size_t)kb * KSLAB);
        const uint4* sg = (const uint4*)(g_G2h + (size_t)kb * KSLAB);
        ((uint4*)k2smraw)[tid] = se[tid];
        ((uint4*)(k2smraw + SM_G2))[tid] = sg[tid];
    }

    int r_lo = lane >> 2;
    int q2 = (lane & 3) * 2;
    int myrow = rowBase + wid * 16;
    __half2 rra = __half2half2(g_rh[myrow + r_lo]);
    __half2 rrb = __half2half2(g_rh[myrow + r_lo + 8]);
    uint32_t bden = (lane < 4) ? 0x3C003C00u : 0u;   // ones column (n-index 0) B-frag

    float acc[8][4];
#pragma unroll
    for (int n = 0; n < 8; n++)
#pragma unroll
        for (int c = 0; c < 4; c++) acc[n][c] = 0.f;
    float accd[4] = {0.f, 0.f, 0.f, 0.f};

    const int* Arow = A + (size_t)myrow * NN + kb * KSLAB;
    int ldRow = lane >> 4;                 // 0..1
    int ldSeg = (lane & 15) * 4;           // int offset 0..60
    uint32_t aRing = sb + SM_A0 + wid * (2 * ASTB);
    const uint4* Bbase = g_Bfrag + (size_t)kb * (KSLAB / 16) * 128 + lane;
    const __half2* E2s = (const __half2*)(k2smraw);
    const __half2* G2s = (const __half2*)(k2smraw + SM_G2);

#define A_STAGE(s) do {                                                           \
        int _c0 = (s) * 64;                                                       \
        uint32_t _ad = aRing + ((s) & 1) * ASTB;                                  \
        _Pragma("unroll")                                                         \
        for (int _L = 0; _L < 8; _L++)                                            \
            cpasync16(_ad + ((_L * 2 + ldRow) * APITCH + ldSeg) * 4,              \
                      Arow + (size_t)(_L * 2 + ldRow) * NN + _c0 + ldSeg);        \
        CP_COMMIT();                                                              \
    } while (0)

    A_STAGE(0);
    A_STAGE(1);

    __syncthreads();   // E2h/G2h visibility (once)

    // B prefetch for chunk 0
    uint4 Bpf[4];
#pragma unroll
    for (int p = 0; p < 4; p++) Bpf[p] = __ldg(Bbase + p * 32);

#pragma unroll 1
    for (int it = 0; it < NIT; ++it) {
        CP_WAIT1();
        __syncwarp();

        const int* Aw = (const int*)(k2smraw + SM_A0 + wid * (2 * ASTB) + (it & 1) * ASTB);

#pragma unroll
        for (int ck = 0; ck < 4; ++ck) {
            int c = it * 4 + ck;
            // consume current prefetch, immediately start next
            uint4 B0 = Bpf[0], B1 = Bpf[1], B2 = Bpf[2], B3 = Bpf[3];
            if (c + 1 < 4 * NIT) {
                const uint4* Bp = Bbase + (size_t)(c + 1) * 128;
#pragma unroll
                for (int p = 0; p < 4; p++) Bpf[p] = __ldg(Bp + p * 32);
            }

            int cl = c * 16;
            __half2 E2a = E2s[(cl + q2) >> 1];
            __half2 G2a = G2s[(cl + q2) >> 1];
            __half2 E2b = E2s[(cl + q2 + 8) >> 1];
            __half2 G2b = G2s[(cl + q2 + 8) >> 1];

            int base = ck * 16 + q2;
            int2 aL0 = *(const int2*)(Aw + r_lo * APITCH + base);
            int2 aL1 = *(const int2*)(Aw + r_lo * APITCH + base + 8);
            int2 aH0 = *(const int2*)(Aw + (r_lo + 8) * APITCH + base);
            int2 aH1 = *(const int2*)(Aw + (r_lo + 8) * APITCH + base + 8);

            // w~ = max(E2', r * G2'), masked by A   (all fp16)
            uint32_t a0 = h2u(__hmax2(E2a, __hmul2(rra, G2a))) & msk2(aL0);
            uint32_t a1 = h2u(__hmax2(E2a, __hmul2(rrb, G2a))) & msk2(aH0);
            uint32_t a2 = h2u(__hmax2(E2b, __hmul2(rra, G2b))) & msk2(aL1);
            uint32_t a3 = h2u(__hmax2(E2b, __hmul2(rrb, G2b))) & msk2(aH1);

            mma16816(acc[0], a0, a1, a2, a3, B0.x, B0.y);
            mma16816(acc[1], a0, a1, a2, a3, B0.z, B0.w);
            mma16816(acc[2], a0, a1, a2, a3, B1.x, B1.y);
            mma16816(acc[3], a0, a1, a2, a3, B1.z, B1.w);
            mma16816(acc[4], a0, a1, a2, a3, B2.x, B2.y);
            mma16816(acc[5], a0, a1, a2, a3, B2.z, B2.w);
            mma16816(acc[6], a0, a1, a2, a3, B3.x, B3.y);
            mma16816(acc[7], a0, a1, a2, a3, B3.z, B3.w);
            mma16816(accd,   a0, a1, a2, a3, bden, bden);   // denominator
        }
        __syncwarp();
        if (it + 2 < NIT) A_STAGE(it + 2);
        else CP_COMMIT();     // keep wait_group accounting uniform
    }

    // denominator: col 0 of accd (exact fp32 sum of the same fp16 w~)
    if ((lane & 3) == 0) {
        g_den[kb * NN + myrow + r_lo] = accd[0];
        g_den[kb * NN + myrow + r_lo + 8] = accd[2];
    }
    // numerator partials
    float* np = g_num + ((size_t)kb * NN + myrow) * OUT_DIM;
#pragma unroll
    for (int nt = 0; nt < 8; nt++) {
        int col = nt * 8 + q2;
        *(float2*)(np + (size_t)r_lo * OUT_DIM + col)       = make_float2(acc[nt][0], acc[nt][1]);
        *(float2*)(np + (size_t)(r_lo + 8) * OUT_DIM + col) = make_float2(acc[nt][2], acc[nt][3]);
    }
}

// ================= K3: reduce, normalize, elu (8 floats/thread) =================
__global__ void k3_fin(float* __restrict__ out) {
    int gid = blockIdx.x * 256 + threadIdx.x;
    int base = gid * 8;
    int row = base >> 6;
    float4 s0 = make_float4(0.f, 0.f, 0.f, 0.f);
    float4 s1 = make_float4(0.f, 0.f, 0.f, 0.f);
    float d = 0.f;
#pragma unroll
    for (int c = 0; c < KB; c++) {
        const float* p = g_num + (size_t)c * NN * OUT_DIM + base;
        float4 v0 = *(const float4*)(p);
        float4 v1 = *(const float4*)(p + 4);
        s0.x += v0.x; s0.y += v0.y; s0.z += v0.z; s0.w += v0.w;
        s1.x += v1.x; s1.y += v1.y; s1.z += v1.z; s1.w += v1.w;
        d += g_den[c * NN + row];
    }
    float inv = 1.f / d;
    float4 o0, o1;
    o0.x = s0.x * inv; o0.y = s0.y * inv; o0.z = s0.z * inv; o0.w = s0.w * inv;
    o1.x = s1.x * inv; o1.y = s1.y * inv; o1.z = s1.z * inv; o1.w = s1.w * inv;
    o0.x = o0.x > 0.f ? o0.x : expm1f(o0.x);
    o0.y = o0.y > 0.f ? o0.y : expm1f(o0.y);
    o0.z = o0.z > 0.f ? o0.z : expm1f(o0.z);
    o0.w = o0.w > 0.f ? o0.w : expm1f(o0.w);
    o1.x = o1.x > 0.f ? o1.x : expm1f(o1.x);
    o1.y = o1.y > 0.f ? o1.y : expm1f(o1.y);
    o1.z = o1.z > 0.f ? o1.z : expm1f(o1.z);
    o1.w = o1.w > 0.f ? o1.w : expm1f(o1.w);
    *(float4*)(out + base) = o0;
    *(float4*)(out + base + 4) = o1;
}

// ================= launch =================
extern "C" void kernel_launch(void* const* d_in, const int* in_sizes, int n_in,
                              void* d_out, int out_size) {
    const float* h = nullptr; const int* A = nullptr;
    const float* W = nullptr; const float* a = nullptr;
    for (int i = 0; i < n_in; i++) {
        if      (in_sizes[i] == NN * IN_DIM)      h = (const float*)d_in[i];
        else if (in_sizes[i] == IN_DIM * OUT_DIM) W = (const float*)d_in[i];
        else if (in_sizes[i] == 2 * OUT_DIM)      a = (const float*)d_in[i];
        else                                      A = (const int*)d_in[i];
    }
    float* out = (float*)d_out;

    const int k1_smem = (IN_DIM * OUT_DIM + 64 * 260) * (int)sizeof(float);  // 132096
    cudaFuncSetAttribute(k1_wh, cudaFuncAttributeMaxDynamicSharedMemorySize, k1_smem);
    const int k2_smem = SM_A0 + 8 * 2 * ASTB;   // 8192 + 69632 = 77824
    cudaFuncSetAttribute(k2_attn, cudaFuncAttributeMaxDynamicSharedMemorySize, k2_smem);

    k1_wh<<<NN / 64, 256, k1_smem>>>(h, W, a);
    k1c<<<NN / 256, 256>>>();
    dnoop<<<1, 32>>>();                       // position k2 as 4th launch for ncu
    dim3 g2(KB, NN / MTILE);
    k2_attn<<<g2, 256, k2_smem>>>(A);
    k3_fin<<<(NN * OUT_DIM) / 2048, 256>>>(out);
}